// round 15
// baseline (speedup 1.0000x reference)
#include <cuda_runtime.h>
#include <cuda_bf16.h>
#include <cstdint>

#define BB 8
#define CC 130
#define CPAD 144          // c padded to 9 x 16 for MMA M tiles
#define CQ 32
#define NN 4096
#define BN_EPS 1e-5f

// ---------------- static device scratch ----------------
__device__ float HF[(size_t)BB * CPAD * NN];            // h fp32 (pre-scale)
__device__ __nv_bfloat16 HHB[(size_t)BB * CPAD * NN];   // h' = h*invZ (bf16)
__device__ __nv_bfloat16 PTH[(size_t)BB * NN * NN];     // e^T: [b][m][n] bf16
__device__ __nv_bfloat16 GTH[(size_t)BB * NN * CQ];     // g^T hi [b][n][32]
__device__ __nv_bfloat16 FTH[(size_t)BB * NN * CQ];     // f^T hi
__device__ float PSUM[(size_t)BB * NN * 64];
__device__ float GNRM[BB * NN];                          // ||g_n||
__device__ int   FMXI[BB];                               // max_m ||f_m||^2 (bits)
__device__ float ROWI[BB * NN];                          // 1/Z

// ---------------- helpers ----------------
__device__ __forceinline__ uint32_t smem_u32(const void* p) {
    uint32_t a;
    asm("{ .reg .u64 t; cvta.to.shared.u64 t, %1; cvt.u32.u64 %0, t; }" : "=r"(a) : "l"(p));
    return a;
}
__device__ __forceinline__ void cpa16(uint32_t dst, const void* src) {
    asm volatile("cp.async.cg.shared.global [%0], [%1], 16;" :: "r"(dst), "l"(src));
}
#define CP_COMMIT() asm volatile("cp.async.commit_group;" ::: "memory")
#define CP_WAIT2()  asm volatile("cp.async.wait_group 2;" ::: "memory")
#define CP_WAIT1()  asm volatile("cp.async.wait_group 1;" ::: "memory")
#define CP_WAIT0()  asm volatile("cp.async.wait_group 0;" ::: "memory")

__device__ __forceinline__ void ldsm4(uint32_t* r, uint32_t addr) {
    asm volatile("ldmatrix.sync.aligned.m8n8.x4.shared.b16 {%0,%1,%2,%3}, [%4];"
                 : "=r"(r[0]), "=r"(r[1]), "=r"(r[2]), "=r"(r[3]) : "r"(addr));
}
__device__ __forceinline__ void ldsm2(uint32_t* r, uint32_t addr) {
    asm volatile("ldmatrix.sync.aligned.m8n8.x2.shared.b16 {%0,%1}, [%2];"
                 : "=r"(r[0]), "=r"(r[1]) : "r"(addr));
}
__device__ __forceinline__ void mma16816(float* d, const uint32_t* a, const uint32_t* b) {
    asm volatile("mma.sync.aligned.m16n8k16.row.col.f32.bf16.bf16.f32 "
                 "{%0,%1,%2,%3}, {%4,%5,%6,%7}, {%8,%9}, {%0,%1,%2,%3};"
                 : "+f"(d[0]), "+f"(d[1]), "+f"(d[2]), "+f"(d[3])
                 : "r"(a[0]), "r"(a[1]), "r"(a[2]), "r"(a[3]), "r"(b[0]), "r"(b[1]));
}

// ---------------------------------------------------------------------------
// K1: fused 1x1-conv + BN + ReLU + norms + bf16 transpose emit (hi only).
// ---------------------------------------------------------------------------
#define WS_OFF (130 * 64 * 4)
#define PROJ_SMEM (WS_OFF + 194 * 132 * 4)
#define STG_ROW 40
#define PS_OFF  (2 * 64 * STG_ROW * 2)

__global__ __launch_bounds__(256) void proj_kernel(
    const float* __restrict__ x,
    const float* __restrict__ wF, const float* __restrict__ bF,
    const float* __restrict__ fw, const float* __restrict__ fbe,
    const float* __restrict__ fm, const float* __restrict__ fv,
    const float* __restrict__ wG, const float* __restrict__ bG,
    const float* __restrict__ gw, const float* __restrict__ gbe,
    const float* __restrict__ gm, const float* __restrict__ gv,
    const float* __restrict__ wH, const float* __restrict__ bH,
    const float* __restrict__ hw, const float* __restrict__ hbe,
    const float* __restrict__ hm, const float* __restrict__ hv)
{
    extern __shared__ char pdyn[];
    float (*xs)[64]  = (float(*)[64])pdyn;
    float (*ws)[132] = (float(*)[132])(pdyn + WS_OFF);
    __nv_bfloat16* stg = (__nv_bfloat16*)(pdyn + WS_OFF);   // aliases ws
    float (*psF)[17] = (float(*)[17])(pdyn + WS_OFF + PS_OFF);
    float (*psG)[17] = (float(*)[17])(pdyn + WS_OFF + PS_OFF + 4352);

    const int b  = blockIdx.y;
    const int n0 = blockIdx.x * 64;
    const int tid = threadIdx.x;

    for (int idx = tid; idx < CC * 64; idx += 256) {
        int c = idx >> 6, i = idx & 63;
        xs[c][i] = x[((size_t)b * CC + c) * NN + n0 + i];
    }
    for (int idx = tid; idx < 194 * 132; idx += 256) {
        int o = idx / 132, c = idx - o * 132;
        float v = 0.f;
        if (c < CC)
            v = (o < CQ) ? wF[o * CC + c]
              : (o < 2 * CQ) ? wG[(o - CQ) * CC + c]
              : wH[(o - 2 * CQ) * CC + c];
        ws[o][c] = v;
    }
    __syncthreads();

    const int tx = tid & 15;
    const int ty = tid >> 4;

    float acc[13][4] = {};

    for (int cc = 0; cc < 128; cc += 8) {
        float4 xv[8];
        #pragma unroll
        for (int j = 0; j < 8; j++)
            xv[j] = *(const float4*)&xs[cc + j][tx * 4];
        #pragma unroll
        for (int oi = 0; oi < 13; oi++) {
            int o = oi * 16 + ty;
            if (o >= 194) continue;
            #pragma unroll
            for (int j2 = 0; j2 < 2; j2++) {
                float4 w4 = *(const float4*)&ws[o][cc + j2 * 4];
                float wv[4] = {w4.x, w4.y, w4.z, w4.w};
                #pragma unroll
                for (int u = 0; u < 4; u++) {
                    float4 xvv = xv[j2 * 4 + u];
                    acc[oi][0] += wv[u] * xvv.x;
                    acc[oi][1] += wv[u] * xvv.y;
                    acc[oi][2] += wv[u] * xvv.z;
                    acc[oi][3] += wv[u] * xvv.w;
                }
            }
        }
    }
    {
        float4 xv0 = *(const float4*)&xs[128][tx * 4];
        float4 xv1 = *(const float4*)&xs[129][tx * 4];
        #pragma unroll
        for (int oi = 0; oi < 13; oi++) {
            int o = oi * 16 + ty;
            if (o >= 194) continue;
            float2 w2 = *(const float2*)&ws[o][128];
            acc[oi][0] += w2.x * xv0.x + w2.y * xv1.x;
            acc[oi][1] += w2.x * xv0.y + w2.y * xv1.y;
            acc[oi][2] += w2.x * xv0.z + w2.y * xv1.z;
            acc[oi][3] += w2.x * xv0.w + w2.y * xv1.w;
        }
    }
    __syncthreads();

    float fsq[4] = {}, gsq[4] = {};
    #pragma unroll
    for (int oi = 0; oi < 13; oi++) {
        int o = oi * 16 + ty;
        if (o >= 194) {
            int oo = o - 2 * CQ;
            *(float4*)&HF[((size_t)b * CPAD + oo) * NN + n0 + tx * 4] =
                make_float4(0.f, 0.f, 0.f, 0.f);
            continue;
        }
        const float *pb, *pw, *pbe, *pm, *pv;
        int oo, which;
        if (o < CQ)          { oo = o;          which = 0; pb = bF; pw = fw; pbe = fbe; pm = fm; pv = fv; }
        else if (o < 2 * CQ) { oo = o - CQ;     which = 1; pb = bG; pw = gw; pbe = gbe; pm = gm; pv = gv; }
        else                 { oo = o - 2 * CQ; which = 2; pb = bH; pw = hw; pbe = hbe; pm = hm; pv = hv; }

        float scale = __ldg(pw + oo) * rsqrtf(__ldg(pv + oo) + BN_EPS);
        float bias  = __ldg(pb + oo) - __ldg(pm + oo);
        float be    = __ldg(pbe + oo);
        float r[4];
        #pragma unroll
        for (int u = 0; u < 4; u++)
            r[u] = fmaxf(scale * (acc[oi][u] + bias) + be, 0.f);

        if (which == 2) {
            *(float4*)&HF[((size_t)b * CPAD + oo) * NN + n0 + tx * 4] =
                make_float4(r[0], r[1], r[2], r[3]);
        } else {
            __nv_bfloat16* sh = stg + which * 64 * STG_ROW;
            #pragma unroll
            for (int u = 0; u < 4; u++) {
                int n = tx * 4 + u;
                sh[n * STG_ROW + oo] = __float2bfloat16(r[u]);
                if (which == 0) fsq[u] += r[u] * r[u];
                else            gsq[u] += r[u] * r[u];
            }
        }
    }
    #pragma unroll
    for (int u = 0; u < 4; u++) {
        psF[tx * 4 + u][ty] = fsq[u];
        psG[tx * 4 + u][ty] = gsq[u];
    }
    __syncthreads();

    if (tid < 64) {
        float fs = 0.f, gs = 0.f;
        #pragma unroll
        for (int t = 0; t < 16; t++) { fs += psF[tid][t]; gs += psG[tid][t]; }
        GNRM[(size_t)b * NN + n0 + tid] = sqrtf(gs);
        #pragma unroll
        for (int off = 16; off; off >>= 1)
            fs = fmaxf(fs, __shfl_xor_sync(0xffffffffu, fs, off));
        if ((tid & 31) == 0)
            atomicMax(&FMXI[b], __float_as_int(fs));
    }

    {
        __nv_bfloat16* dsts[2] = {
            FTH + ((size_t)b * NN + n0) * CQ, GTH + ((size_t)b * NN + n0) * CQ };
        #pragma unroll
        for (int rpt = 0; rpt < 2; rpt++) {
            int i = tid + rpt * 256;
            int arr = i >> 8, idx = i & 255, row = idx >> 2, q = idx & 3;
            uint4 v = *(const uint4*)&stg[arr * 64 * STG_ROW + row * STG_ROW + q * 8];
            *(uint4*)&dsts[arr][row * CQ + q * 8] = v;
        }
    }
}

// ---------------------------------------------------------------------------
// K2: S (hi x hi single pass) + e = exp(S - M~) -> PTH (transposed via smem)
//     + per-(row, 64-m) sum partials into PSUM[.., 64].
// Block: 128n x 256m (two 128-m halves, serial); 8 warps (4n x 2m per half).
// ---------------------------------------------------------------------------
#define PE 136
#define SE_ESM (3 * 10240)
#define SE_SMEM (SE_ESM + 128 * PE * 2)    // 30720 + 34816 = 65536

__global__ __launch_bounds__(256) void gemm_se_kernel()
{
    extern __shared__ char dyn[];
    const uint32_t sb = smem_u32(dyn);
    __nv_bfloat16* esm = (__nv_bfloat16*)(dyn + SE_ESM);

    const int b  = blockIdx.z;
    const int m0 = blockIdx.x * 256;
    const int n0 = blockIdx.y * 128;
    const int tid = threadIdx.x;

    {
        const __nv_bfloat16* srcs[3] = {
            GTH + ((size_t)b * NN + n0) * CQ,
            FTH + ((size_t)b * NN + m0) * CQ,
            FTH + ((size_t)b * NN + m0 + 128) * CQ };
        #pragma unroll
        for (int r = 0; r < 6; r++) {
            int t = tid + r * 256;
            int buf = t >> 9, idx = t & 511, row = idx >> 2, q = idx & 3;
            cpa16(sb + buf * 10240 + row * 80 + q * 16, srcs[buf] + row * CQ + q * 8);
        }
    }
    CP_COMMIT();
    CP_WAIT0();
    __syncthreads();

    const int w = tid >> 5, lane = tid & 31;
    const int nw = w >> 1, mw = w & 1;
    const int a_roff = ((lane >> 3) & 1) * 8 + (lane & 7);
    const int a_koff = lane >> 4;
    const int bl = lane & 15;
    const int b_roff = bl & 7, b_koff = bl >> 3;

    const uint32_t gh_b = sb;
    const float fmaxn = sqrtf(__int_as_float(FMXI[b]));
    const int g = lane >> 2, q = (lane & 3) * 2;
    const int nch = lane & 15;

    for (int half = 0; half < 2; half++) {
        const uint32_t fh_b = sb + 10240 + half * 10240;

        float acc[2][8][4] = {};
        #pragma unroll
        for (int ks = 0; ks < 2; ks++) {
            uint32_t Ah[2][4], Bh[8][2];
            #pragma unroll
            for (int at = 0; at < 2; at++) {
                int row = nw * 32 + at * 16 + a_roff;
                ldsm4(Ah[at], gh_b + row * 80 + ks * 32 + a_koff * 16);
            }
            #pragma unroll
            for (int bt = 0; bt < 8; bt++) {
                int row = mw * 64 + bt * 8 + b_roff;
                ldsm2(Bh[bt], fh_b + row * 80 + ks * 32 + b_koff * 16);
            }
            #pragma unroll
            for (int at = 0; at < 2; at++)
                #pragma unroll
                for (int bt = 0; bt < 8; bt++)
                    mma16816(acc[at][bt], Ah[at], Bh[bt]);
        }

        #pragma unroll
        for (int at = 0; at < 2; at++) {
            int nl_lo = nw * 32 + at * 16 + g;
            int nl_hi = nl_lo + 8;
            float Mlo = GNRM[(size_t)b * NN + n0 + nl_lo] * fmaxn;
            float Mhi = GNRM[(size_t)b * NN + n0 + nl_hi] * fmaxn;
            float s_lo = 0.f, s_hi = 0.f;
            #pragma unroll
            for (int bt = 0; bt < 8; bt++) {
                int ml = mw * 64 + bt * 8 + q;
                float e0 = __expf(acc[at][bt][0] - Mlo);
                float e1 = __expf(acc[at][bt][1] - Mlo);
                float e2 = __expf(acc[at][bt][2] - Mhi);
                float e3 = __expf(acc[at][bt][3] - Mhi);
                esm[(ml    ) * PE + nl_lo] = __float2bfloat16(e0);
                esm[(ml + 1) * PE + nl_lo] = __float2bfloat16(e1);
                esm[(ml    ) * PE + nl_hi] = __float2bfloat16(e2);
                esm[(ml + 1) * PE + nl_hi] = __float2bfloat16(e3);
                s_lo += e0 + e1;
                s_hi += e2 + e3;
            }
            s_lo += __shfl_xor_sync(0xffffffffu, s_lo, 1);
            s_lo += __shfl_xor_sync(0xffffffffu, s_lo, 2);
            s_hi += __shfl_xor_sync(0xffffffffu, s_hi, 1);
            s_hi += __shfl_xor_sync(0xffffffffu, s_hi, 2);
            if ((lane & 3) == 0) {
                int col = blockIdx.x * 4 + half * 2 + mw;
                PSUM[((size_t)b * NN + n0 + nl_lo) * 64 + col] = s_lo;
                PSUM[((size_t)b * NN + n0 + nl_hi) * 64 + col] = s_hi;
            }
        }
        __syncthreads();

        #pragma unroll
        for (int it = 0; it < 8; it++) {
            int ml = it * 16 + w * 2 + (lane >> 4);
            uint4 v = *(const uint4*)&esm[ml * PE + nch * 8];
            size_t dst = ((size_t)b * NN + m0 + half * 128 + ml) * NN + n0 + nch * 8;
            *(uint4*)&PTH[dst] = v;
        }
        __syncthreads();
    }
}

// ---------------------------------------------------------------------------
// K2b: ROWI = 1 / sum of 64 partials
// ---------------------------------------------------------------------------
__global__ __launch_bounds__(256) void reduce_sum_kernel()
{
    int r = blockIdx.x * 8 + (threadIdx.x >> 5);
    int lane = threadIdx.x & 31;
    const float* ps = PSUM + (size_t)r * 64;
    float z = ps[lane] + ps[lane + 32];
    #pragma unroll
    for (int off = 16; off; off >>= 1)
        z += __shfl_xor_sync(0xffffffffu, z, off);
    if (lane == 0) ROWI[r] = 1.f / z;
}

// ---------------------------------------------------------------------------
// K3: h'[b,c,n] = HF[b,c,n] * ROWI[b,n] -> bf16
// ---------------------------------------------------------------------------
__global__ __launch_bounds__(256) void scale_h_kernel()
{
    const int b = blockIdx.x / CPAD;
    const int c = blockIdx.x % CPAD;
    const float* hrow = HF + ((size_t)b * CPAD + c) * NN;
    const float* zrow = ROWI + (size_t)b * NN;
    __nv_bfloat16* dh = HHB + ((size_t)b * CPAD + c) * NN;

    for (int i = threadIdx.x; i < NN / 4; i += 256) {
        float4 h = *(const float4*)&hrow[i * 4];
        float4 z = *(const float4*)&zrow[i * 4];
        __nv_bfloat16 hi[4];
        hi[0] = __float2bfloat16(h.x * z.x);
        hi[1] = __float2bfloat16(h.y * z.y);
        hi[2] = __float2bfloat16(h.z * z.z);
        hi[3] = __float2bfloat16(h.w * z.w);
        *(uint2*)&dh[i * 4] = *(uint2*)hi;
    }
}

// ---------------------------------------------------------------------------
// K4: mma.sync GEMM (single pass, 3-stage ring, 2 CTAs/SM).
// D[c(144), m(128)] = H'[c,:] e[:,m];  out = gamma * D + x.
// 3 x 34816 B x 2 CTAs = ~209 KB < 228 KB SM smem -> occupancy retained;
// CP_WAIT2 keeps two loads in flight (covers DRAM latency per chunk).
// ---------------------------------------------------------------------------
#define KB 64
#define ST_AH 0
#define ST_BH 18432
#define ST_BYTES 34816
#define SMEM_DYN (3 * ST_BYTES)

__global__ __launch_bounds__(256, 2) void gemm_o_mma_kernel(
    const float* __restrict__ x, const float* __restrict__ gamma,
    float* __restrict__ out)
{
    extern __shared__ __align__(128) char smem_raw[];
    const uint32_t sb = smem_u32(smem_raw);

    const int tid  = threadIdx.x;
    const int w    = tid >> 5;
    const int lane = tid & 31;
    const int cw   = w >> 2;
    const int mw   = w & 3;
    const int nct  = (cw == 0) ? 5 : 4;
    const int b    = blockIdx.y;
    const int m0   = blockIdx.x * 128;

    const size_t abase = (size_t)b * CPAD;
    const size_t bbase = (size_t)b * NN + m0;

    auto load_stage = [&](int st, int nk) {
        uint32_t base = sb + st * ST_BYTES;
        for (int t = tid; t < 1152; t += 256) {
            int row = t >> 3, q = t & 7;
            const __nv_bfloat16* src = HHB + ((abase + row) << 12) + nk + q * 8;
            cpa16(base + ST_AH + row * 128 + ((q ^ (row & 7)) << 4), src);
        }
        for (int t = tid; t < 1024; t += 256) {
            int row = t >> 3, q = t & 7;
            const __nv_bfloat16* src = PTH + ((bbase + row) << 12) + nk + q * 8;
            cpa16(base + ST_BH + row * 128 + ((q ^ (row & 7)) << 4), src);
        }
    };

    float acc[5][4][4] = {};

    load_stage(0, 0);
    CP_COMMIT();
    load_stage(1, KB);
    CP_COMMIT();

    const int a_roff = ((lane >> 3) & 1) * 8 + (lane & 7);
    const int a_koff = lane >> 4;
    const int bl     = lane & 15;
    const int b_roff = bl & 7;
    const int b_koff = bl >> 3;

    for (int chunk = 0; chunk < NN / KB; chunk++) {
        int cur = chunk % 3;
        if (chunk + 2 < NN / KB) {
            load_stage((chunk + 2) % 3, (chunk + 2) * KB);
            CP_COMMIT();
            CP_WAIT2();
        } else if (chunk + 1 < NN / KB) {
            CP_WAIT1();
        } else {
            CP_WAIT0();
        }
        __syncthreads();

        uint32_t base = sb + cur * ST_BYTES;
        #pragma unroll
        for (int ks = 0; ks < 4; ks++) {
            uint32_t Bh[4][2];
            #pragma unroll
            for (int mt = 0; mt < 4; mt++) {
                int row = mw * 32 + mt * 8 + b_roff;
                int kch = ks * 2 + b_koff;
                ldsm2(Bh[mt], base + ST_BH + row * 128 + ((kch ^ (row & 7)) << 4));
            }
            #pragma unroll
            for (int ct = 0; ct < 5; ct++) {
                if (ct < nct) {
                    uint32_t Ah[4];
                    int row = cw * 80 + ct * 16 + a_roff;
                    int kch = ks * 2 + a_koff;
                    ldsm4(Ah, base + ST_AH + row * 128 + ((kch ^ (row & 7)) << 4));
                    #pragma unroll
                    for (int mt = 0; mt < 4; mt++)
                        mma16816(acc[ct][mt], Ah, Bh[mt]);
                }
            }
        }
        __syncthreads();
    }

    const float gm = __ldg(gamma);
    const int g = lane >> 2;
    const int mo = (lane & 3) * 2;
    #pragma unroll
    for (int ct = 0; ct < 5; ct++) {
        if (ct >= nct) break;
        int c0 = cw * 80 + ct * 16 + g;
        #pragma unroll
        for (int mt = 0; mt < 4; mt++) {
            int m = m0 + mw * 32 + mt * 8 + mo;
            if (c0 < CC) {
                size_t idx = ((size_t)b * CC + c0) * NN + m;
                float2 xv = *(const float2*)&x[idx];
                *(float2*)&out[idx] = make_float2(gm * acc[ct][mt][0] + xv.x,
                                                  gm * acc[ct][mt][1] + xv.y);
            }
            if (c0 + 8 < CC) {
                size_t idx = ((size_t)b * CC + c0 + 8) * NN + m;
                float2 xv = *(const float2*)&x[idx];
                *(float2*)&out[idx] = make_float2(gm * acc[ct][mt][2] + xv.x,
                                                  gm * acc[ct][mt][3] + xv.y);
            }
        }
    }
}

// ---------------------------------------------------------------------------
extern "C" void kernel_launch(void* const* d_in, const int* in_sizes, int n_in,
                              void* d_out, int out_size)
{
    const float* x   = (const float*)d_in[0];
    const float* wF  = (const float*)d_in[1];
    const float* bF  = (const float*)d_in[2];
    const float* fw  = (const float*)d_in[3];
    const float* fbe = (const float*)d_in[4];
    const float* fm  = (const float*)d_in[5];
    const float* fv  = (const float*)d_in[6];
    const float* wG  = (const float*)d_in[7];
    const float* bG  = (const float*)d_in[8];
    const float* gw  = (const float*)d_in[9];
    const float* gbe = (const float*)d_in[10];
    const float* gm  = (const float*)d_in[11];
    const float* gv  = (const float*)d_in[12];
    const float* wH  = (const float*)d_in[13];
    const float* bH  = (const float*)d_in[14];
    const float* hw  = (const float*)d_in[15];
    const float* hbe = (const float*)d_in[16];
    const float* hm  = (const float*)d_in[17];
    const float* hv  = (const float*)d_in[18];
    const float* gamma = (const float*)d_in[19];
    float* out = (float*)d_out;

    cudaFuncSetAttribute(proj_kernel,
                         cudaFuncAttributeMaxDynamicSharedMemorySize, PROJ_SMEM);
    cudaFuncSetAttribute(gemm_se_kernel,
                         cudaFuncAttributeMaxDynamicSharedMemorySize, SE_SMEM);
    cudaFuncSetAttribute(gemm_o_mma_kernel,
                         cudaFuncAttributeMaxDynamicSharedMemorySize, SMEM_DYN);

    proj_kernel<<<dim3(NN / 64, BB), 256, PROJ_SMEM>>>(x,
        wF, bF, fw, fbe, fm, fv,
        wG, bG, gw, gbe, gm, gv,
        wH, bH, hw, hbe, hm, hv);
    gemm_se_kernel<<<dim3(NN / 256, NN / 128, BB), 256, SE_SMEM>>>();
    reduce_sum_kernel<<<BB * NN / 8, 256>>>();
    scale_h_kernel<<<BB * CPAD, 256>>>();
    gemm_o_mma_kernel<<<dim3(NN / 128, BB), 256, SMEM_DYN>>>(x, gamma, out);
}

// round 16
// speedup vs baseline: 1.0132x; 1.0132x over previous
#include <cuda_runtime.h>
#include <cuda_bf16.h>
#include <cstdint>

#define BB 8
#define CC 130
#define CPAD 144          // c padded to 9 x 16 for MMA M tiles
#define CQ 32
#define NN 4096
#define BN_EPS 1e-5f

// ---------------- static device scratch ----------------
__device__ float HF[(size_t)BB * CPAD * NN];            // h fp32 (pre-scale)
__device__ __nv_bfloat16 HHB[(size_t)BB * CPAD * NN];   // h' = h*invZ (bf16)
__device__ __nv_bfloat16 PTH[(size_t)BB * NN * NN];     // e^T: [b][m][n] bf16
__device__ __nv_bfloat16 GTH[(size_t)BB * NN * CQ];     // g^T hi [b][n][32]
__device__ __nv_bfloat16 FTH[(size_t)BB * NN * CQ];     // f^T hi
__device__ float PSUM[(size_t)BB * NN * 64];
__device__ float GNRM[BB * NN];                          // ||g_n||
__device__ int   FMXI[BB];                               // max_m ||f_m||^2 (bits)
__device__ float ROWI[BB * NN];                          // 1/Z

// ---------------- helpers ----------------
__device__ __forceinline__ uint32_t smem_u32(const void* p) {
    uint32_t a;
    asm("{ .reg .u64 t; cvta.to.shared.u64 t, %1; cvt.u32.u64 %0, t; }" : "=r"(a) : "l"(p));
    return a;
}
__device__ __forceinline__ void cpa16(uint32_t dst, const void* src) {
    asm volatile("cp.async.cg.shared.global [%0], [%1], 16;" :: "r"(dst), "l"(src));
}
#define CP_COMMIT() asm volatile("cp.async.commit_group;" ::: "memory")
#define CP_WAIT1()  asm volatile("cp.async.wait_group 1;" ::: "memory")
#define CP_WAIT0()  asm volatile("cp.async.wait_group 0;" ::: "memory")

__device__ __forceinline__ void ldsm4(uint32_t* r, uint32_t addr) {
    asm volatile("ldmatrix.sync.aligned.m8n8.x4.shared.b16 {%0,%1,%2,%3}, [%4];"
                 : "=r"(r[0]), "=r"(r[1]), "=r"(r[2]), "=r"(r[3]) : "r"(addr));
}
__device__ __forceinline__ void ldsm2(uint32_t* r, uint32_t addr) {
    asm volatile("ldmatrix.sync.aligned.m8n8.x2.shared.b16 {%0,%1}, [%2];"
                 : "=r"(r[0]), "=r"(r[1]) : "r"(addr));
}
__device__ __forceinline__ void mma16816(float* d, const uint32_t* a, const uint32_t* b) {
    asm volatile("mma.sync.aligned.m16n8k16.row.col.f32.bf16.bf16.f32 "
                 "{%0,%1,%2,%3}, {%4,%5,%6,%7}, {%8,%9}, {%0,%1,%2,%3};"
                 : "+f"(d[0]), "+f"(d[1]), "+f"(d[2]), "+f"(d[3])
                 : "r"(a[0]), "r"(a[1]), "r"(a[2]), "r"(a[3]), "r"(b[0]), "r"(b[1]));
}

// ---------------------------------------------------------------------------
// K1: fused 1x1-conv + BN + ReLU + norms + bf16 transpose emit (hi only).
// ---------------------------------------------------------------------------
#define WS_OFF (130 * 64 * 4)
#define PROJ_SMEM (WS_OFF + 194 * 132 * 4)
#define STG_ROW 40
#define PS_OFF  (2 * 64 * STG_ROW * 2)

__global__ __launch_bounds__(256) void proj_kernel(
    const float* __restrict__ x,
    const float* __restrict__ wF, const float* __restrict__ bF,
    const float* __restrict__ fw, const float* __restrict__ fbe,
    const float* __restrict__ fm, const float* __restrict__ fv,
    const float* __restrict__ wG, const float* __restrict__ bG,
    const float* __restrict__ gw, const float* __restrict__ gbe,
    const float* __restrict__ gm, const float* __restrict__ gv,
    const float* __restrict__ wH, const float* __restrict__ bH,
    const float* __restrict__ hw, const float* __restrict__ hbe,
    const float* __restrict__ hm, const float* __restrict__ hv)
{
    extern __shared__ char pdyn[];
    float (*xs)[64]  = (float(*)[64])pdyn;
    float (*ws)[132] = (float(*)[132])(pdyn + WS_OFF);
    __nv_bfloat16* stg = (__nv_bfloat16*)(pdyn + WS_OFF);   // aliases ws
    float (*psF)[17] = (float(*)[17])(pdyn + WS_OFF + PS_OFF);
    float (*psG)[17] = (float(*)[17])(pdyn + WS_OFF + PS_OFF + 4352);

    const int b  = blockIdx.y;
    const int n0 = blockIdx.x * 64;
    const int tid = threadIdx.x;

    for (int idx = tid; idx < CC * 64; idx += 256) {
        int c = idx >> 6, i = idx & 63;
        xs[c][i] = x[((size_t)b * CC + c) * NN + n0 + i];
    }
    for (int idx = tid; idx < 194 * 132; idx += 256) {
        int o = idx / 132, c = idx - o * 132;
        float v = 0.f;
        if (c < CC)
            v = (o < CQ) ? wF[o * CC + c]
              : (o < 2 * CQ) ? wG[(o - CQ) * CC + c]
              : wH[(o - 2 * CQ) * CC + c];
        ws[o][c] = v;
    }
    __syncthreads();

    const int tx = tid & 15;
    const int ty = tid >> 4;

    float acc[13][4] = {};

    for (int cc = 0; cc < 128; cc += 8) {
        float4 xv[8];
        #pragma unroll
        for (int j = 0; j < 8; j++)
            xv[j] = *(const float4*)&xs[cc + j][tx * 4];
        #pragma unroll
        for (int oi = 0; oi < 13; oi++) {
            int o = oi * 16 + ty;
            if (o >= 194) continue;
            #pragma unroll
            for (int j2 = 0; j2 < 2; j2++) {
                float4 w4 = *(const float4*)&ws[o][cc + j2 * 4];
                float wv[4] = {w4.x, w4.y, w4.z, w4.w};
                #pragma unroll
                for (int u = 0; u < 4; u++) {
                    float4 xvv = xv[j2 * 4 + u];
                    acc[oi][0] += wv[u] * xvv.x;
                    acc[oi][1] += wv[u] * xvv.y;
                    acc[oi][2] += wv[u] * xvv.z;
                    acc[oi][3] += wv[u] * xvv.w;
                }
            }
        }
    }
    {
        float4 xv0 = *(const float4*)&xs[128][tx * 4];
        float4 xv1 = *(const float4*)&xs[129][tx * 4];
        #pragma unroll
        for (int oi = 0; oi < 13; oi++) {
            int o = oi * 16 + ty;
            if (o >= 194) continue;
            float2 w2 = *(const float2*)&ws[o][128];
            acc[oi][0] += w2.x * xv0.x + w2.y * xv1.x;
            acc[oi][1] += w2.x * xv0.y + w2.y * xv1.y;
            acc[oi][2] += w2.x * xv0.z + w2.y * xv1.z;
            acc[oi][3] += w2.x * xv0.w + w2.y * xv1.w;
        }
    }
    __syncthreads();

    float fsq[4] = {}, gsq[4] = {};
    #pragma unroll
    for (int oi = 0; oi < 13; oi++) {
        int o = oi * 16 + ty;
        if (o >= 194) {
            int oo = o - 2 * CQ;
            *(float4*)&HF[((size_t)b * CPAD + oo) * NN + n0 + tx * 4] =
                make_float4(0.f, 0.f, 0.f, 0.f);
            continue;
        }
        const float *pb, *pw, *pbe, *pm, *pv;
        int oo, which;
        if (o < CQ)          { oo = o;          which = 0; pb = bF; pw = fw; pbe = fbe; pm = fm; pv = fv; }
        else if (o < 2 * CQ) { oo = o - CQ;     which = 1; pb = bG; pw = gw; pbe = gbe; pm = gm; pv = gv; }
        else                 { oo = o - 2 * CQ; which = 2; pb = bH; pw = hw; pbe = hbe; pm = hm; pv = hv; }

        float scale = __ldg(pw + oo) * rsqrtf(__ldg(pv + oo) + BN_EPS);
        float bias  = __ldg(pb + oo) - __ldg(pm + oo);
        float be    = __ldg(pbe + oo);
        float r[4];
        #pragma unroll
        for (int u = 0; u < 4; u++)
            r[u] = fmaxf(scale * (acc[oi][u] + bias) + be, 0.f);

        if (which == 2) {
            *(float4*)&HF[((size_t)b * CPAD + oo) * NN + n0 + tx * 4] =
                make_float4(r[0], r[1], r[2], r[3]);
        } else {
            __nv_bfloat16* sh = stg + which * 64 * STG_ROW;
            #pragma unroll
            for (int u = 0; u < 4; u++) {
                int n = tx * 4 + u;
                sh[n * STG_ROW + oo] = __float2bfloat16(r[u]);
                if (which == 0) fsq[u] += r[u] * r[u];
                else            gsq[u] += r[u] * r[u];
            }
        }
    }
    #pragma unroll
    for (int u = 0; u < 4; u++) {
        psF[tx * 4 + u][ty] = fsq[u];
        psG[tx * 4 + u][ty] = gsq[u];
    }
    __syncthreads();

    if (tid < 64) {
        float fs = 0.f, gs = 0.f;
        #pragma unroll
        for (int t = 0; t < 16; t++) { fs += psF[tid][t]; gs += psG[tid][t]; }
        GNRM[(size_t)b * NN + n0 + tid] = sqrtf(gs);
        #pragma unroll
        for (int off = 16; off; off >>= 1)
            fs = fmaxf(fs, __shfl_xor_sync(0xffffffffu, fs, off));
        if ((tid & 31) == 0)
            atomicMax(&FMXI[b], __float_as_int(fs));
    }

    {
        __nv_bfloat16* dsts[2] = {
            FTH + ((size_t)b * NN + n0) * CQ, GTH + ((size_t)b * NN + n0) * CQ };
        #pragma unroll
        for (int rpt = 0; rpt < 2; rpt++) {
            int i = tid + rpt * 256;
            int arr = i >> 8, idx = i & 255, row = idx >> 2, q = idx & 3;
            uint4 v = *(const uint4*)&stg[arr * 64 * STG_ROW + row * STG_ROW + q * 8];
            *(uint4*)&dsts[arr][row * CQ + q * 8] = v;
        }
    }
}

// ---------------------------------------------------------------------------
// K2: S (hi x hi single pass) + e = exp(S - M~) -> PTH (transposed via smem)
//     + per-(row, 64-m) sum partials into PSUM[.., 64].
// Block: 128n x 256m (two 128-m halves, serial); 8 warps (4n x 2m per half).
// ---------------------------------------------------------------------------
#define PE 136
#define SE_ESM (3 * 10240)
#define SE_SMEM (SE_ESM + 128 * PE * 2)    // 30720 + 34816 = 65536

__global__ __launch_bounds__(256) void gemm_se_kernel()
{
    extern __shared__ char dyn[];
    const uint32_t sb = smem_u32(dyn);
    __nv_bfloat16* esm = (__nv_bfloat16*)(dyn + SE_ESM);

    const int b  = blockIdx.z;
    const int m0 = blockIdx.x * 256;
    const int n0 = blockIdx.y * 128;
    const int tid = threadIdx.x;

    {
        const __nv_bfloat16* srcs[3] = {
            GTH + ((size_t)b * NN + n0) * CQ,
            FTH + ((size_t)b * NN + m0) * CQ,
            FTH + ((size_t)b * NN + m0 + 128) * CQ };
        #pragma unroll
        for (int r = 0; r < 6; r++) {
            int t = tid + r * 256;
            int buf = t >> 9, idx = t & 511, row = idx >> 2, q = idx & 3;
            cpa16(sb + buf * 10240 + row * 80 + q * 16, srcs[buf] + row * CQ + q * 8);
        }
    }
    CP_COMMIT();
    CP_WAIT0();
    __syncthreads();

    const int w = tid >> 5, lane = tid & 31;
    const int nw = w >> 1, mw = w & 1;
    const int a_roff = ((lane >> 3) & 1) * 8 + (lane & 7);
    const int a_koff = lane >> 4;
    const int bl = lane & 15;
    const int b_roff = bl & 7, b_koff = bl >> 3;

    const uint32_t gh_b = sb;
    const float fmaxn = sqrtf(__int_as_float(FMXI[b]));
    const int g = lane >> 2, q = (lane & 3) * 2;
    const int nch = lane & 15;

    for (int half = 0; half < 2; half++) {
        const uint32_t fh_b = sb + 10240 + half * 10240;

        float acc[2][8][4] = {};
        #pragma unroll
        for (int ks = 0; ks < 2; ks++) {
            uint32_t Ah[2][4], Bh[8][2];
            #pragma unroll
            for (int at = 0; at < 2; at++) {
                int row = nw * 32 + at * 16 + a_roff;
                ldsm4(Ah[at], gh_b + row * 80 + ks * 32 + a_koff * 16);
            }
            #pragma unroll
            for (int bt = 0; bt < 8; bt++) {
                int row = mw * 64 + bt * 8 + b_roff;
                ldsm2(Bh[bt], fh_b + row * 80 + ks * 32 + b_koff * 16);
            }
            #pragma unroll
            for (int at = 0; at < 2; at++)
                #pragma unroll
                for (int bt = 0; bt < 8; bt++)
                    mma16816(acc[at][bt], Ah[at], Bh[bt]);
        }

        #pragma unroll
        for (int at = 0; at < 2; at++) {
            int nl_lo = nw * 32 + at * 16 + g;
            int nl_hi = nl_lo + 8;
            float Mlo = GNRM[(size_t)b * NN + n0 + nl_lo] * fmaxn;
            float Mhi = GNRM[(size_t)b * NN + n0 + nl_hi] * fmaxn;
            float s_lo = 0.f, s_hi = 0.f;
            #pragma unroll
            for (int bt = 0; bt < 8; bt++) {
                int ml = mw * 64 + bt * 8 + q;
                float e0 = __expf(acc[at][bt][0] - Mlo);
                float e1 = __expf(acc[at][bt][1] - Mlo);
                float e2 = __expf(acc[at][bt][2] - Mhi);
                float e3 = __expf(acc[at][bt][3] - Mhi);
                esm[(ml    ) * PE + nl_lo] = __float2bfloat16(e0);
                esm[(ml + 1) * PE + nl_lo] = __float2bfloat16(e1);
                esm[(ml    ) * PE + nl_hi] = __float2bfloat16(e2);
                esm[(ml + 1) * PE + nl_hi] = __float2bfloat16(e3);
                s_lo += e0 + e1;
                s_hi += e2 + e3;
            }
            s_lo += __shfl_xor_sync(0xffffffffu, s_lo, 1);
            s_lo += __shfl_xor_sync(0xffffffffu, s_lo, 2);
            s_hi += __shfl_xor_sync(0xffffffffu, s_hi, 1);
            s_hi += __shfl_xor_sync(0xffffffffu, s_hi, 2);
            if ((lane & 3) == 0) {
                int col = blockIdx.x * 4 + half * 2 + mw;
                PSUM[((size_t)b * NN + n0 + nl_lo) * 64 + col] = s_lo;
                PSUM[((size_t)b * NN + n0 + nl_hi) * 64 + col] = s_hi;
            }
        }
        __syncthreads();

        #pragma unroll
        for (int it = 0; it < 8; it++) {
            int ml = it * 16 + w * 2 + (lane >> 4);
            uint4 v = *(const uint4*)&esm[ml * PE + nch * 8];
            size_t dst = ((size_t)b * NN + m0 + half * 128 + ml) * NN + n0 + nch * 8;
            *(uint4*)&PTH[dst] = v;
        }
        __syncthreads();
    }
}

// ---------------------------------------------------------------------------
// K2b: ROWI = 1 / sum of 64 partials
// ---------------------------------------------------------------------------
__global__ __launch_bounds__(256) void reduce_sum_kernel()
{
    int r = blockIdx.x * 8 + (threadIdx.x >> 5);
    int lane = threadIdx.x & 31;
    const float* ps = PSUM + (size_t)r * 64;
    float z = ps[lane] + ps[lane + 32];
    #pragma unroll
    for (int off = 16; off; off >>= 1)
        z += __shfl_xor_sync(0xffffffffu, z, off);
    if (lane == 0) ROWI[r] = 1.f / z;
}

// ---------------------------------------------------------------------------
// K3: h'[b,c,n] = HF[b,c,n] * ROWI[b,n] -> bf16
// ---------------------------------------------------------------------------
__global__ __launch_bounds__(256) void scale_h_kernel()
{
    const int b = blockIdx.x / CPAD;
    const int c = blockIdx.x % CPAD;
    const float* hrow = HF + ((size_t)b * CPAD + c) * NN;
    const float* zrow = ROWI + (size_t)b * NN;
    __nv_bfloat16* dh = HHB + ((size_t)b * CPAD + c) * NN;

    for (int i = threadIdx.x; i < NN / 4; i += 256) {
        float4 h = *(const float4*)&hrow[i * 4];
        float4 z = *(const float4*)&zrow[i * 4];
        __nv_bfloat16 hi[4];
        hi[0] = __float2bfloat16(h.x * z.x);
        hi[1] = __float2bfloat16(h.y * z.y);
        hi[2] = __float2bfloat16(h.z * z.z);
        hi[3] = __float2bfloat16(h.w * z.w);
        *(uint2*)&dh[i * 4] = *(uint2*)hi;
    }
}

// ---------------------------------------------------------------------------
// K4: mma.sync GEMM (single pass, 2-stage, 384 thr = 12 warps: 3 cw x 4 mw).
// D[c(144), m(128)] = H'[c,:] e[:,m];  out = gamma * D + x.
// Each warp: exactly 3 c-tiles (no imbalance); acc 48 regs; 85-reg budget at
// 2 CTAs/SM -> 24 warps/SM for HMMA latency hiding.
// ---------------------------------------------------------------------------
#define KB 64
#define ST_AH 0
#define ST_BH 18432
#define ST_BYTES 34816
#define SMEM_DYN (2 * ST_BYTES)

__global__ __launch_bounds__(384, 2) void gemm_o_mma_kernel(
    const float* __restrict__ x, const float* __restrict__ gamma,
    float* __restrict__ out)
{
    extern __shared__ __align__(128) char smem_raw[];
    const uint32_t sb = smem_u32(smem_raw);

    const int tid  = threadIdx.x;
    const int w    = tid >> 5;
    const int lane = tid & 31;
    const int cw   = w >> 2;           // 0..2
    const int mw   = w & 3;            // 0..3
    const int b    = blockIdx.y;
    const int m0   = blockIdx.x * 128;

    const size_t abase = (size_t)b * CPAD;
    const size_t bbase = (size_t)b * NN + m0;

    auto load_stage = [&](int st, int nk) {
        uint32_t base = sb + st * ST_BYTES;
        for (int t = tid; t < 1152; t += 384) {
            int row = t >> 3, q = t & 7;
            const __nv_bfloat16* src = HHB + ((abase + row) << 12) + nk + q * 8;
            cpa16(base + ST_AH + row * 128 + ((q ^ (row & 7)) << 4), src);
        }
        for (int t = tid; t < 1024; t += 384) {
            int row = t >> 3, q = t & 7;
            const __nv_bfloat16* src = PTH + ((bbase + row) << 12) + nk + q * 8;
            cpa16(base + ST_BH + row * 128 + ((q ^ (row & 7)) << 4), src);
        }
    };

    float acc[3][4][4] = {};

    load_stage(0, 0);
    CP_COMMIT();

    const int a_roff = ((lane >> 3) & 1) * 8 + (lane & 7);
    const int a_koff = lane >> 4;
    const int bl     = lane & 15;
    const int b_roff = bl & 7;
    const int b_koff = bl >> 3;

    for (int chunk = 0; chunk < NN / KB; chunk++) {
        int cur = chunk & 1;
        if (chunk + 1 < NN / KB) {
            load_stage(cur ^ 1, (chunk + 1) * KB);
            CP_COMMIT();
            CP_WAIT1();
        } else {
            CP_WAIT0();
        }
        __syncthreads();

        uint32_t base = sb + cur * ST_BYTES;
        #pragma unroll
        for (int ks = 0; ks < 4; ks++) {
            uint32_t Bh[4][2];
            #pragma unroll
            for (int mt = 0; mt < 4; mt++) {
                int row = mw * 32 + mt * 8 + b_roff;
                int kch = ks * 2 + b_koff;
                ldsm2(Bh[mt], base + ST_BH + row * 128 + ((kch ^ (row & 7)) << 4));
            }
            #pragma unroll
            for (int ct = 0; ct < 3; ct++) {
                uint32_t Ah[4];
                int row = cw * 48 + ct * 16 + a_roff;
                int kch = ks * 2 + a_koff;
                ldsm4(Ah, base + ST_AH + row * 128 + ((kch ^ (row & 7)) << 4));
                #pragma unroll
                for (int mt = 0; mt < 4; mt++)
                    mma16816(acc[ct][mt], Ah, Bh[mt]);
            }
        }
        __syncthreads();
    }

    const float gm = __ldg(gamma);
    const int g = lane >> 2;
    const int mo = (lane & 3) * 2;
    #pragma unroll
    for (int ct = 0; ct < 3; ct++) {
        int c0 = cw * 48 + ct * 16 + g;
        #pragma unroll
        for (int mt = 0; mt < 4; mt++) {
            int m = m0 + mw * 32 + mt * 8 + mo;
            if (c0 < CC) {
                size_t idx = ((size_t)b * CC + c0) * NN + m;
                float2 xv = *(const float2*)&x[idx];
                *(float2*)&out[idx] = make_float2(gm * acc[ct][mt][0] + xv.x,
                                                  gm * acc[ct][mt][1] + xv.y);
            }
            if (c0 + 8 < CC) {
                size_t idx = ((size_t)b * CC + c0 + 8) * NN + m;
                float2 xv = *(const float2*)&x[idx];
                *(float2*)&out[idx] = make_float2(gm * acc[ct][mt][2] + xv.x,
                                                  gm * acc[ct][mt][3] + xv.y);
            }
        }
    }
}

// ---------------------------------------------------------------------------
extern "C" void kernel_launch(void* const* d_in, const int* in_sizes, int n_in,
                              void* d_out, int out_size)
{
    const float* x   = (const float*)d_in[0];
    const float* wF  = (const float*)d_in[1];
    const float* bF  = (const float*)d_in[2];
    const float* fw  = (const float*)d_in[3];
    const float* fbe = (const float*)d_in[4];
    const float* fm  = (const float*)d_in[5];
    const float* fv  = (const float*)d_in[6];
    const float* wG  = (const float*)d_in[7];
    const float* bG  = (const float*)d_in[8];
    const float* gw  = (const float*)d_in[9];
    const float* gbe = (const float*)d_in[10];
    const float* gm  = (const float*)d_in[11];
    const float* gv  = (const float*)d_in[12];
    const float* wH  = (const float*)d_in[13];
    const float* bH  = (const float*)d_in[14];
    const float* hw  = (const float*)d_in[15];
    const float* hbe = (const float*)d_in[16];
    const float* hm  = (const float*)d_in[17];
    const float* hv  = (const float*)d_in[18];
    const float* gamma = (const float*)d_in[19];
    float* out = (float*)d_out;

    cudaFuncSetAttribute(proj_kernel,
                         cudaFuncAttributeMaxDynamicSharedMemorySize, PROJ_SMEM);
    cudaFuncSetAttribute(gemm_se_kernel,
                         cudaFuncAttributeMaxDynamicSharedMemorySize, SE_SMEM);
    cudaFuncSetAttribute(gemm_o_mma_kernel,
                         cudaFuncAttributeMaxDynamicSharedMemorySize, SMEM_DYN);

    proj_kernel<<<dim3(NN / 64, BB), 256, PROJ_SMEM>>>(x,
        wF, bF, fw, fbe, fm, fv,
        wG, bG, gw, gbe, gm, gv,
        wH, bH, hw, hbe, hm, hv);
    gemm_se_kernel<<<dim3(NN / 256, NN / 128, BB), 256, SE_SMEM>>>();
    reduce_sum_kernel<<<BB * NN / 8, 256>>>();
    scale_h_kernel<<<BB * CPAD, 256>>>();
    gemm_o_mma_kernel<<<dim3(NN / 128, BB), 384, SMEM_DYN>>>(x, gamma, out);
}

// round 17
// speedup vs baseline: 1.2970x; 1.2802x over previous
#include <cuda_runtime.h>
#include <cuda_bf16.h>
#include <cstdint>

#define BB 8
#define CC 130
#define CPAD 144          // c padded to 9 x 16 for MMA M tiles
#define CQ 32
#define NN 4096
#define BN_EPS 1e-5f

// ---------------- static device scratch ----------------
__device__ float HF[(size_t)BB * CPAD * NN];            // h fp32 (pre-scale)
__device__ __nv_bfloat16 HHB[(size_t)BB * CPAD * NN];   // h' = h*invZ (bf16)
__device__ __nv_bfloat16 PTH[(size_t)BB * NN * NN];     // e^T: [b][m][n] bf16
__device__ __nv_bfloat16 GTH[(size_t)BB * NN * CQ];     // g^T hi [b][n][32]
__device__ __nv_bfloat16 FTH[(size_t)BB * NN * CQ];     // f^T hi
__device__ float PSUM[(size_t)BB * NN * 64];
__device__ float GNRM[BB * NN];                          // ||g_n||
__device__ int   FMXI[BB];                               // max_m ||f_m||^2 (bits)
__device__ float ROWI[BB * NN];                          // 1/Z
__device__ __align__(16) float WS[194 * 132];            // packed aligned weights

// ---------------- helpers ----------------
__device__ __forceinline__ uint32_t smem_u32(const void* p) {
    uint32_t a;
    asm("{ .reg .u64 t; cvta.to.shared.u64 t, %1; cvt.u32.u64 %0, t; }" : "=r"(a) : "l"(p));
    return a;
}
__device__ __forceinline__ void cpa16(uint32_t dst, const void* src) {
    asm volatile("cp.async.cg.shared.global [%0], [%1], 16;" :: "r"(dst), "l"(src));
}
#define CP_COMMIT() asm volatile("cp.async.commit_group;" ::: "memory")
#define CP_WAIT1()  asm volatile("cp.async.wait_group 1;" ::: "memory")
#define CP_WAIT0()  asm volatile("cp.async.wait_group 0;" ::: "memory")

__device__ __forceinline__ void ldsm4(uint32_t* r, uint32_t addr) {
    asm volatile("ldmatrix.sync.aligned.m8n8.x4.shared.b16 {%0,%1,%2,%3}, [%4];"
                 : "=r"(r[0]), "=r"(r[1]), "=r"(r[2]), "=r"(r[3]) : "r"(addr));
}
__device__ __forceinline__ void ldsm2(uint32_t* r, uint32_t addr) {
    asm volatile("ldmatrix.sync.aligned.m8n8.x2.shared.b16 {%0,%1}, [%2];"
                 : "=r"(r[0]), "=r"(r[1]) : "r"(addr));
}
__device__ __forceinline__ void mma16816(float* d, const uint32_t* a, const uint32_t* b) {
    asm volatile("mma.sync.aligned.m16n8k16.row.col.f32.bf16.bf16.f32 "
                 "{%0,%1,%2,%3}, {%4,%5,%6,%7}, {%8,%9}, {%0,%1,%2,%3};"
                 : "+f"(d[0]), "+f"(d[1]), "+f"(d[2]), "+f"(d[3])
                 : "r"(a[0]), "r"(a[1]), "r"(a[2]), "r"(a[3]), "r"(b[0]), "r"(b[1]));
}

// ---------------------------------------------------------------------------
// K0: pack weights into aligned padded WS[194][132]
// rows: 0..31 F, 32..63 G, 64..193 H; cols >= 130 zero.
// ---------------------------------------------------------------------------
__global__ __launch_bounds__(256) void pack_w_kernel(
    const float* __restrict__ wF, const float* __restrict__ wG,
    const float* __restrict__ wH)
{
    int idx = blockIdx.x * 256 + threadIdx.x;
    if (idx >= 194 * 132) return;
    int o = idx / 132, c = idx - o * 132;
    float v = 0.f;
    if (c < CC)
        v = (o < CQ) ? wF[o * CC + c]
          : (o < 2 * CQ) ? wG[(o - CQ) * CC + c]
          : wH[(o - 2 * CQ) * CC + c];
    WS[idx] = v;
}

// ---------------------------------------------------------------------------
// K1: fused 1x1-conv + BN + ReLU + norms + bf16 transpose emit (hi only).
// Weights streamed from WS via __ldg (broadcast, L1-resident); smem only 33 KB
// (xs tile, aliased after the main loop by bf16 staging + norm partials).
// ---------------------------------------------------------------------------
#define PROJ_SMEM (130 * 64 * 4)
#define STG_ROW 40
#define PS_OFF  (2 * 64 * STG_ROW * 2)

__global__ __launch_bounds__(256, 2) void proj_kernel(
    const float* __restrict__ x,
    const float* __restrict__ bF,
    const float* __restrict__ fw, const float* __restrict__ fbe,
    const float* __restrict__ fm, const float* __restrict__ fv,
    const float* __restrict__ bG,
    const float* __restrict__ gw, const float* __restrict__ gbe,
    const float* __restrict__ gm, const float* __restrict__ gv,
    const float* __restrict__ bH,
    const float* __restrict__ hw, const float* __restrict__ hbe,
    const float* __restrict__ hm, const float* __restrict__ hv)
{
    extern __shared__ char pdyn[];
    float (*xs)[64]  = (float(*)[64])pdyn;
    __nv_bfloat16* stg = (__nv_bfloat16*)pdyn;               // aliases xs (after)
    float (*psF)[17] = (float(*)[17])(pdyn + PS_OFF);
    float (*psG)[17] = (float(*)[17])(pdyn + PS_OFF + 4352);

    const int b  = blockIdx.y;
    const int n0 = blockIdx.x * 64;
    const int tid = threadIdx.x;

    for (int idx = tid; idx < CC * 64; idx += 256) {
        int c = idx >> 6, i = idx & 63;
        xs[c][i] = x[((size_t)b * CC + c) * NN + n0 + i];
    }
    __syncthreads();

    const int tx = tid & 15;
    const int ty = tid >> 4;

    float acc[13][4] = {};

    for (int cc = 0; cc < 128; cc += 8) {
        float4 xv[8];
        #pragma unroll
        for (int j = 0; j < 8; j++)
            xv[j] = *(const float4*)&xs[cc + j][tx * 4];
        #pragma unroll
        for (int oi = 0; oi < 13; oi++) {
            int o = oi * 16 + ty;
            if (o >= 194) continue;
            #pragma unroll
            for (int j2 = 0; j2 < 2; j2++) {
                float4 w4 = __ldg((const float4*)&WS[o * 132 + cc + j2 * 4]);
                float wv[4] = {w4.x, w4.y, w4.z, w4.w};
                #pragma unroll
                for (int u = 0; u < 4; u++) {
                    float4 xvv = xv[j2 * 4 + u];
                    acc[oi][0] += wv[u] * xvv.x;
                    acc[oi][1] += wv[u] * xvv.y;
                    acc[oi][2] += wv[u] * xvv.z;
                    acc[oi][3] += wv[u] * xvv.w;
                }
            }
        }
    }
    {
        float4 xv0 = *(const float4*)&xs[128][tx * 4];
        float4 xv1 = *(const float4*)&xs[129][tx * 4];
        #pragma unroll
        for (int oi = 0; oi < 13; oi++) {
            int o = oi * 16 + ty;
            if (o >= 194) continue;
            float2 w2 = __ldg((const float2*)&WS[o * 132 + 128]);
            acc[oi][0] += w2.x * xv0.x + w2.y * xv1.x;
            acc[oi][1] += w2.x * xv0.y + w2.y * xv1.y;
            acc[oi][2] += w2.x * xv0.z + w2.y * xv1.z;
            acc[oi][3] += w2.x * xv0.w + w2.y * xv1.w;
        }
    }
    __syncthreads();   // all xs reads done before staging overwrites it

    float fsq[4] = {}, gsq[4] = {};
    #pragma unroll
    for (int oi = 0; oi < 13; oi++) {
        int o = oi * 16 + ty;
        if (o >= 194) {
            int oo = o - 2 * CQ;
            *(float4*)&HF[((size_t)b * CPAD + oo) * NN + n0 + tx * 4] =
                make_float4(0.f, 0.f, 0.f, 0.f);
            continue;
        }
        const float *pb, *pw, *pbe, *pm, *pv;
        int oo, which;
        if (o < CQ)          { oo = o;          which = 0; pb = bF; pw = fw; pbe = fbe; pm = fm; pv = fv; }
        else if (o < 2 * CQ) { oo = o - CQ;     which = 1; pb = bG; pw = gw; pbe = gbe; pm = gm; pv = gv; }
        else                 { oo = o - 2 * CQ; which = 2; pb = bH; pw = hw; pbe = hbe; pm = hm; pv = hv; }

        float scale = __ldg(pw + oo) * rsqrtf(__ldg(pv + oo) + BN_EPS);
        float bias  = __ldg(pb + oo) - __ldg(pm + oo);
        float be    = __ldg(pbe + oo);
        float r[4];
        #pragma unroll
        for (int u = 0; u < 4; u++)
            r[u] = fmaxf(scale * (acc[oi][u] + bias) + be, 0.f);

        if (which == 2) {
            *(float4*)&HF[((size_t)b * CPAD + oo) * NN + n0 + tx * 4] =
                make_float4(r[0], r[1], r[2], r[3]);
        } else {
            __nv_bfloat16* sh = stg + which * 64 * STG_ROW;
            #pragma unroll
            for (int u = 0; u < 4; u++) {
                int n = tx * 4 + u;
                sh[n * STG_ROW + oo] = __float2bfloat16(r[u]);
                if (which == 0) fsq[u] += r[u] * r[u];
                else            gsq[u] += r[u] * r[u];
            }
        }
    }
    #pragma unroll
    for (int u = 0; u < 4; u++) {
        psF[tx * 4 + u][ty] = fsq[u];
        psG[tx * 4 + u][ty] = gsq[u];
    }
    __syncthreads();

    if (tid < 64) {
        float fs = 0.f, gs = 0.f;
        #pragma unroll
        for (int t = 0; t < 16; t++) { fs += psF[tid][t]; gs += psG[tid][t]; }
        GNRM[(size_t)b * NN + n0 + tid] = sqrtf(gs);
        #pragma unroll
        for (int off = 16; off; off >>= 1)
            fs = fmaxf(fs, __shfl_xor_sync(0xffffffffu, fs, off));
        if ((tid & 31) == 0)
            atomicMax(&FMXI[b], __float_as_int(fs));
    }

    {
        __nv_bfloat16* dsts[2] = {
            FTH + ((size_t)b * NN + n0) * CQ, GTH + ((size_t)b * NN + n0) * CQ };
        #pragma unroll
        for (int rpt = 0; rpt < 2; rpt++) {
            int i = tid + rpt * 256;
            int arr = i >> 8, idx = i & 255, row = idx >> 2, q = idx & 3;
            uint4 v = *(const uint4*)&stg[arr * 64 * STG_ROW + row * STG_ROW + q * 8];
            *(uint4*)&dsts[arr][row * CQ + q * 8] = v;
        }
    }
}

// ---------------------------------------------------------------------------
// K2: S (hi x hi single pass) + e = exp(S - M~) -> PTH (transposed via smem)
//     + per-(row, 64-m) sum partials into PSUM[.., 64].
// Block: 128n x 256m (two 128-m halves, serial); 8 warps (4n x 2m per half).
// ---------------------------------------------------------------------------
#define PE 136
#define SE_ESM (3 * 10240)
#define SE_SMEM (SE_ESM + 128 * PE * 2)    // 30720 + 34816 = 65536

__global__ __launch_bounds__(256) void gemm_se_kernel()
{
    extern __shared__ char dyn[];
    const uint32_t sb = smem_u32(dyn);
    __nv_bfloat16* esm = (__nv_bfloat16*)(dyn + SE_ESM);

    const int b  = blockIdx.z;
    const int m0 = blockIdx.x * 256;
    const int n0 = blockIdx.y * 128;
    const int tid = threadIdx.x;

    {
        const __nv_bfloat16* srcs[3] = {
            GTH + ((size_t)b * NN + n0) * CQ,
            FTH + ((size_t)b * NN + m0) * CQ,
            FTH + ((size_t)b * NN + m0 + 128) * CQ };
        #pragma unroll
        for (int r = 0; r < 6; r++) {
            int t = tid + r * 256;
            int buf = t >> 9, idx = t & 511, row = idx >> 2, q = idx & 3;
            cpa16(sb + buf * 10240 + row * 80 + q * 16, srcs[buf] + row * CQ + q * 8);
        }
    }
    CP_COMMIT();
    CP_WAIT0();
    __syncthreads();

    const int w = tid >> 5, lane = tid & 31;
    const int nw = w >> 1, mw = w & 1;
    const int a_roff = ((lane >> 3) & 1) * 8 + (lane & 7);
    const int a_koff = lane >> 4;
    const int bl = lane & 15;
    const int b_roff = bl & 7, b_koff = bl >> 3;

    const uint32_t gh_b = sb;
    const float fmaxn = sqrtf(__int_as_float(FMXI[b]));
    const int g = lane >> 2, q = (lane & 3) * 2;
    const int nch = lane & 15;

    for (int half = 0; half < 2; half++) {
        const uint32_t fh_b = sb + 10240 + half * 10240;

        float acc[2][8][4] = {};
        #pragma unroll
        for (int ks = 0; ks < 2; ks++) {
            uint32_t Ah[2][4], Bh[8][2];
            #pragma unroll
            for (int at = 0; at < 2; at++) {
                int row = nw * 32 + at * 16 + a_roff;
                ldsm4(Ah[at], gh_b + row * 80 + ks * 32 + a_koff * 16);
            }
            #pragma unroll
            for (int bt = 0; bt < 8; bt++) {
                int row = mw * 64 + bt * 8 + b_roff;
                ldsm2(Bh[bt], fh_b + row * 80 + ks * 32 + b_koff * 16);
            }
            #pragma unroll
            for (int at = 0; at < 2; at++)
                #pragma unroll
                for (int bt = 0; bt < 8; bt++)
                    mma16816(acc[at][bt], Ah[at], Bh[bt]);
        }

        #pragma unroll
        for (int at = 0; at < 2; at++) {
            int nl_lo = nw * 32 + at * 16 + g;
            int nl_hi = nl_lo + 8;
            float Mlo = GNRM[(size_t)b * NN + n0 + nl_lo] * fmaxn;
            float Mhi = GNRM[(size_t)b * NN + n0 + nl_hi] * fmaxn;
            float s_lo = 0.f, s_hi = 0.f;
            #pragma unroll
            for (int bt = 0; bt < 8; bt++) {
                int ml = mw * 64 + bt * 8 + q;
                float e0 = __expf(acc[at][bt][0] - Mlo);
                float e1 = __expf(acc[at][bt][1] - Mlo);
                float e2 = __expf(acc[at][bt][2] - Mhi);
                float e3 = __expf(acc[at][bt][3] - Mhi);
                esm[(ml    ) * PE + nl_lo] = __float2bfloat16(e0);
                esm[(ml + 1) * PE + nl_lo] = __float2bfloat16(e1);
                esm[(ml    ) * PE + nl_hi] = __float2bfloat16(e2);
                esm[(ml + 1) * PE + nl_hi] = __float2bfloat16(e3);
                s_lo += e0 + e1;
                s_hi += e2 + e3;
            }
            s_lo += __shfl_xor_sync(0xffffffffu, s_lo, 1);
            s_lo += __shfl_xor_sync(0xffffffffu, s_lo, 2);
            s_hi += __shfl_xor_sync(0xffffffffu, s_hi, 1);
            s_hi += __shfl_xor_sync(0xffffffffu, s_hi, 2);
            if ((lane & 3) == 0) {
                int col = blockIdx.x * 4 + half * 2 + mw;
                PSUM[((size_t)b * NN + n0 + nl_lo) * 64 + col] = s_lo;
                PSUM[((size_t)b * NN + n0 + nl_hi) * 64 + col] = s_hi;
            }
        }
        __syncthreads();

        #pragma unroll
        for (int it = 0; it < 8; it++) {
            int ml = it * 16 + w * 2 + (lane >> 4);
            uint4 v = *(const uint4*)&esm[ml * PE + nch * 8];
            size_t dst = ((size_t)b * NN + m0 + half * 128 + ml) * NN + n0 + nch * 8;
            *(uint4*)&PTH[dst] = v;
        }
        __syncthreads();
    }
}

// ---------------------------------------------------------------------------
// K2b: ROWI = 1 / sum of 64 partials
// ---------------------------------------------------------------------------
__global__ __launch_bounds__(256) void reduce_sum_kernel()
{
    int r = blockIdx.x * 8 + (threadIdx.x >> 5);
    int lane = threadIdx.x & 31;
    const float* ps = PSUM + (size_t)r * 64;
    float z = ps[lane] + ps[lane + 32];
    #pragma unroll
    for (int off = 16; off; off >>= 1)
        z += __shfl_xor_sync(0xffffffffu, z, off);
    if (lane == 0) ROWI[r] = 1.f / z;
}

// ---------------------------------------------------------------------------
// K3: h'[b,c,n] = HF[b,c,n] * ROWI[b,n] -> bf16
// ---------------------------------------------------------------------------
__global__ __launch_bounds__(256) void scale_h_kernel()
{
    const int b = blockIdx.x / CPAD;
    const int c = blockIdx.x % CPAD;
    const float* hrow = HF + ((size_t)b * CPAD + c) * NN;
    const float* zrow = ROWI + (size_t)b * NN;
    __nv_bfloat16* dh = HHB + ((size_t)b * CPAD + c) * NN;

    for (int i = threadIdx.x; i < NN / 4; i += 256) {
        float4 h = *(const float4*)&hrow[i * 4];
        float4 z = *(const float4*)&zrow[i * 4];
        __nv_bfloat16 hi[4];
        hi[0] = __float2bfloat16(h.x * z.x);
        hi[1] = __float2bfloat16(h.y * z.y);
        hi[2] = __float2bfloat16(h.z * z.z);
        hi[3] = __float2bfloat16(h.w * z.w);
        *(uint2*)&dh[i * 4] = *(uint2*)hi;
    }
}

// ---------------------------------------------------------------------------
// K4: mma.sync GEMM (single pass, 2-stage, 384 thr = 12 warps: 3 cw x 4 mw).
// D[c(144), m(128)] = H'[c,:] e[:,m];  out = gamma * D + x.
// ---------------------------------------------------------------------------
#define KB 64
#define ST_AH 0
#define ST_BH 18432
#define ST_BYTES 34816
#define SMEM_DYN (2 * ST_BYTES)

__global__ __launch_bounds__(384, 2) void gemm_o_mma_kernel(
    const float* __restrict__ x, const float* __restrict__ gamma,
    float* __restrict__ out)
{
    extern __shared__ __align__(128) char smem_raw[];
    const uint32_t sb = smem_u32(smem_raw);

    const int tid  = threadIdx.x;
    const int w    = tid >> 5;
    const int lane = tid & 31;
    const int cw   = w >> 2;           // 0..2
    const int mw   = w & 3;            // 0..3
    const int b    = blockIdx.y;
    const int m0   = blockIdx.x * 128;

    const size_t abase = (size_t)b * CPAD;
    const size_t bbase = (size_t)b * NN + m0;

    auto load_stage = [&](int st, int nk) {
        uint32_t base = sb + st * ST_BYTES;
        for (int t = tid; t < 1152; t += 384) {
            int row = t >> 3, q = t & 7;
            const __nv_bfloat16* src = HHB + ((abase + row) << 12) + nk + q * 8;
            cpa16(base + ST_AH + row * 128 + ((q ^ (row & 7)) << 4), src);
        }
        for (int t = tid; t < 1024; t += 384) {
            int row = t >> 3, q = t & 7;
            const __nv_bfloat16* src = PTH + ((bbase + row) << 12) + nk + q * 8;
            cpa16(base + ST_BH + row * 128 + ((q ^ (row & 7)) << 4), src);
        }
    };

    float acc[3][4][4] = {};

    load_stage(0, 0);
    CP_COMMIT();

    const int a_roff = ((lane >> 3) & 1) * 8 + (lane & 7);
    const int a_koff = lane >> 4;
    const int bl     = lane & 15;
    const int b_roff = bl & 7;
    const int b_koff = bl >> 3;

    for (int chunk = 0; chunk < NN / KB; chunk++) {
        int cur = chunk & 1;
        if (chunk + 1 < NN / KB) {
            load_stage(cur ^ 1, (chunk + 1) * KB);
            CP_COMMIT();
            CP_WAIT1();
        } else {
            CP_WAIT0();
        }
        __syncthreads();

        uint32_t base = sb + cur * ST_BYTES;
        #pragma unroll
        for (int ks = 0; ks < 4; ks++) {
            uint32_t Bh[4][2];
            #pragma unroll
            for (int mt = 0; mt < 4; mt++) {
                int row = mw * 32 + mt * 8 + b_roff;
                int kch = ks * 2 + b_koff;
                ldsm2(Bh[mt], base + ST_BH + row * 128 + ((kch ^ (row & 7)) << 4));
            }
            #pragma unroll
            for (int ct = 0; ct < 3; ct++) {
                uint32_t Ah[4];
                int row = cw * 48 + ct * 16 + a_roff;
                int kch = ks * 2 + a_koff;
                ldsm4(Ah, base + ST_AH + row * 128 + ((kch ^ (row & 7)) << 4));
                #pragma unroll
                for (int mt = 0; mt < 4; mt++)
                    mma16816(acc[ct][mt], Ah, Bh[mt]);
            }
        }
        __syncthreads();
    }

    const float gm = __ldg(gamma);
    const int g = lane >> 2;
    const int mo = (lane & 3) * 2;
    #pragma unroll
    for (int ct = 0; ct < 3; ct++) {
        int c0 = cw * 48 + ct * 16 + g;
        #pragma unroll
        for (int mt = 0; mt < 4; mt++) {
            int m = m0 + mw * 32 + mt * 8 + mo;
            if (c0 < CC) {
                size_t idx = ((size_t)b * CC + c0) * NN + m;
                float2 xv = *(const float2*)&x[idx];
                *(float2*)&out[idx] = make_float2(gm * acc[ct][mt][0] + xv.x,
                                                  gm * acc[ct][mt][1] + xv.y);
            }
            if (c0 + 8 < CC) {
                size_t idx = ((size_t)b * CC + c0 + 8) * NN + m;
                float2 xv = *(const float2*)&x[idx];
                *(float2*)&out[idx] = make_float2(gm * acc[ct][mt][2] + xv.x,
                                                  gm * acc[ct][mt][3] + xv.y);
            }
        }
    }
}

// ---------------------------------------------------------------------------
extern "C" void kernel_launch(void* const* d_in, const int* in_sizes, int n_in,
                              void* d_out, int out_size)
{
    const float* x   = (const float*)d_in[0];
    const float* wF  = (const float*)d_in[1];
    const float* bF  = (const float*)d_in[2];
    const float* fw  = (const float*)d_in[3];
    const float* fbe = (const float*)d_in[4];
    const float* fm  = (const float*)d_in[5];
    const float* fv  = (const float*)d_in[6];
    const float* wG  = (const float*)d_in[7];
    const float* bG  = (const float*)d_in[8];
    const float* gw  = (const float*)d_in[9];
    const float* gbe = (const float*)d_in[10];
    const float* gm  = (const float*)d_in[11];
    const float* gv  = (const float*)d_in[12];
    const float* wH  = (const float*)d_in[13];
    const float* bH  = (const float*)d_in[14];
    const float* hw  = (const float*)d_in[15];
    const float* hbe = (const float*)d_in[16];
    const float* hm  = (const float*)d_in[17];
    const float* hv  = (const float*)d_in[18];
    const float* gamma = (const float*)d_in[19];
    float* out = (float*)d_out;

    cudaFuncSetAttribute(proj_kernel,
                         cudaFuncAttributeMaxDynamicSharedMemorySize, PROJ_SMEM);
    cudaFuncSetAttribute(gemm_se_kernel,
                         cudaFuncAttributeMaxDynamicSharedMemorySize, SE_SMEM);
    cudaFuncSetAttribute(gemm_o_mma_kernel,
                         cudaFuncAttributeMaxDynamicSharedMemorySize, SMEM_DYN);

    pack_w_kernel<<<(194 * 132 + 255) / 256, 256>>>(wF, wG, wH);
    proj_kernel<<<dim3(NN / 64, BB), 256, PROJ_SMEM>>>(x,
        bF, fw, fbe, fm, fv,
        bG, gw, gbe, gm, gv,
        bH, hw, hbe, hm, hv);
    gemm_se_kernel<<<dim3(NN / 256, NN / 128, BB), 256, SE_SMEM>>>();
    reduce_sum_kernel<<<BB * NN / 8, 256>>>();
    scale_h_kernel<<<BB * CPAD, 256>>>();
    gemm_o_mma_kernel<<<dim3(NN / 128, BB), 384, SMEM_DYN>>>(x, gamma, out);
}